// round 7
// baseline (speedup 1.0000x reference)
#include <cuda_runtime.h>

// (B, D, H, W) = (2, 192, 192, 192) fp32
#define DD 192
#define HH 192
#define WW 192
#define PLANE 36864
#define VOL   7077888

#define TH     16          // output tile height (h)
#define TW     32          // output tile width  (w)
#define INROWS 24          // TH + 8 halo
#define DCHUNK 96
#define NT     256
#define SWSTR  33          // float4 stride, conflict-free

#define INV_VOL (1.0f / 729.0f)
#define EPS 1e-5f

// Fully fused 9^3 LNCC, tuned for 2 CTAs/SM:
//  W-stage: 192 threads load 12-wide windows (3 aligned float4 x 2 fields)
//           from gmem, emit 4 sliding W-sums each as packed float4 to smem.
//  H-stage: 256 threads read 10 float4 rows -> 2 HW-sums each.
//  D-stage: 8-deep register ring + fused epilogue.
__global__ void __launch_bounds__(NT, 2)
lncc_fused3(const float* __restrict__ gt,
            const float* __restrict__ gp,
            float* __restrict__ out)
{
    __shared__ float4 s_w[2][INROWS][SWSTR];   // (st, sp, stp, pad) 25.3 KB

    const int tid = threadIdx.x;
    const int bx  = blockIdx.x;
    const int wt  = bx % 6;
    const int ht  = (bx / 6) % 12;
    const int dc  = (bx / 72) % 2;
    const int b   = bx / 144;
    const int w0 = wt * TW, h0 = ht * TH, d0 = dc * DCHUNK;

    // ---- W-stage geometry: 24 rows x 8 segments of 4 outputs = 192 ----
    const bool wact = tid < 192;
    const int wr   = tid >> 3;             // 0..23
    const int wseg = tid & 7;              // 0..7
    const int gh   = h0 - 4 + wr;
    const int gw0  = w0 + wseg * 4 - 4;    // float4 aligned
    const bool hok = wact && (unsigned)gh < HH;
    const int rowbase = b * VOL + gh * WW;
    bool cok[3];
#pragma unroll
    for (int c = 0; c < 3; ++c)
        cok[c] = hok && (gw0 + c * 4 >= 0) && (gw0 + c * 4 < WW);

    float4 Pt[3], Pp[3];

    auto prefetch = [&](int dz) {
        const bool dok = (unsigned)dz < DD;
        const int base = rowbase + dz * PLANE + gw0;
#pragma unroll
        for (int c = 0; c < 3; ++c) {
            if (dok && cok[c]) {
                Pt[c] = *(const float4*)(gt + base + c * 4);
                Pp[c] = *(const float4*)(gp + base + c * 4);
            } else {
                Pt[c] = make_float4(0.f, 0.f, 0.f, 0.f);
                Pp[c] = make_float4(0.f, 0.f, 0.f, 0.f);
            }
        }
    };

    auto wstore = [&](int bsel) {
        if (!wact) return;
        const float t[12] = {Pt[0].x, Pt[0].y, Pt[0].z, Pt[0].w,
                             Pt[1].x, Pt[1].y, Pt[1].z, Pt[1].w,
                             Pt[2].x, Pt[2].y, Pt[2].z, Pt[2].w};
        const float p[12] = {Pp[0].x, Pp[0].y, Pp[0].z, Pp[0].w,
                             Pp[1].x, Pp[1].y, Pp[1].z, Pp[1].w,
                             Pp[2].x, Pp[2].y, Pp[2].z, Pp[2].w};
        float m[12];
#pragma unroll
        for (int k = 0; k < 12; ++k) m[k] = t[k] * p[k];

        float st = 0.f, sp = 0.f, stp = 0.f;
#pragma unroll
        for (int k = 0; k < 9; ++k) { st += t[k]; sp += p[k]; stp += m[k]; }
        const int ow = wseg * 4;
        s_w[bsel][wr][ow] = make_float4(st, sp, stp, 0.f);
#pragma unroll
        for (int q = 1; q < 4; ++q) {
            st  += t[8 + q] - t[q - 1];
            sp  += p[8 + q] - p[q - 1];
            stp += m[8 + q] - m[q - 1];
            s_w[bsel][wr][ow + q] = make_float4(st, sp, stp, 0.f);
        }
    };

    // ---- H-stage geometry: 2 consecutive h-outputs per thread ----
    const int ty = tid >> 5;      // 0..7
    const int tx = tid & 31;
    const int rb = ty << 1;       // 0..14

    auto h_stage = [&](int bsel,
                       float& a0, float& a1, float& a2,
                       float& b0, float& b1, float& b2) {
        const float4 v0 = s_w[bsel][rb][tx];
        a0 = v0.x; a1 = v0.y; a2 = v0.z;
#pragma unroll
        for (int k = 1; k < 9; ++k) {
            const float4 v = s_w[bsel][rb + k][tx];
            a0 += v.x; a1 += v.y; a2 += v.z;
        }
        const float4 v9 = s_w[bsel][rb + 9][tx];
        b0 = a0 - v0.x + v9.x;
        b1 = a1 - v0.y + v9.y;
        b2 = a2 - v0.z + v9.z;
    };

    // ---- D ring: 8 deep x 3 fields x 2 outputs ----
    float r0a[8], r1a[8], r2a[8], r0b[8], r1b[8], r2b[8];
#pragma unroll
    for (int i = 0; i < 8; ++i) {
        r0a[i] = r1a[i] = r2a[i] = 0.f;
        r0b[i] = r1b[i] = r2b[i] = 0.f;
    }
    float s0a = 0.f, s1a = 0.f, s2a = 0.f;
    float s0b = 0.f, s1b = 0.f, s2b = 0.f;

    int buf = 0;
    prefetch(d0 - 4);

    // ---- warmup: ingest slices d0-4 .. d0+3 ----
#pragma unroll
    for (int i = 0; i < 8; ++i) {
        wstore(buf);
        prefetch(d0 - 3 + i);
        __syncthreads();
        float a0, a1, a2, b0, b1, b2;
        h_stage(buf, a0, a1, a2, b0, b1, b2);
        r0a[i] = a0; r1a[i] = a1; r2a[i] = a2;
        r0b[i] = b0; r1b[i] = b1; r2b[i] = b2;
        s0a += a0; s1a += a1; s2a += a2;
        s0b += b0; s1b += b1; s2b += b2;
        buf ^= 1;
    }

    // ---- main loop: outputs d0 .. d0+95 ----
    const int ob = b * VOL + (h0 + rb) * WW + w0 + tx;
    for (int s8 = 0; s8 < DCHUNK / 8; ++s8) {
#pragma unroll
        for (int ph = 0; ph < 8; ++ph) {
            const int step = s8 * 8 + ph;
            wstore(buf);                  // slice d0+4+step
            prefetch(d0 + 5 + step);
            __syncthreads();
            float a0, a1, a2, b0, b1, b2;
            h_stage(buf, a0, a1, a2, b0, b1, b2);
            s0a += a0; s1a += a1; s2a += a2;
            s0b += b0; s1b += b1; s2b += b2;

            const float ca = s2a - s1a * s0a * INV_VOL;
            const float cb = s2b - s1b * s0b * INV_VOL;
            const int o = ob + (d0 + step) * PLANE;
            out[o]      = fmaf(ca, ca, EPS);
            out[o + WW] = fmaf(cb, cb, EPS);

            s0a -= r0a[ph]; r0a[ph] = a0;
            s1a -= r1a[ph]; r1a[ph] = a1;
            s2a -= r2a[ph]; r2a[ph] = a2;
            s0b -= r0b[ph]; r0b[ph] = b0;
            s1b -= r1b[ph]; r1b[ph] = b1;
            s2b -= r2b[ph]; r2b[ph] = b2;
            buf ^= 1;
        }
    }
}

extern "C" void kernel_launch(void* const* d_in, const int* in_sizes, int n_in,
                              void* d_out, int out_size) {
    const float* y_true = (const float*)d_in[0];
    const float* y_pred = (const float*)d_in[1];
    float* out = (float*)d_out;

    // 6 w-tiles x 12 h-tiles x 2 d-chunks x 2 batches = 288 blocks
    lncc_fused3<<<288, NT>>>(y_true, y_pred, out);
}

// round 8
// speedup vs baseline: 1.2012x; 1.2012x over previous
#include <cuda_runtime.h>
#include <cstdint>

// (B, D, H, W) = (2, 192, 192, 192) fp32
#define DD 192
#define HH 192
#define WW 192
#define PLANE 36864
#define VOL   7077888

#define NT     256
#define DCHUNK 96
#define ST_ROW 44                    // stage row stride (floats), 16B-aligned
#define ST_FIELD (40 * ST_ROW)       // 1760 floats
#define ST_BUF   (2 * ST_FIELD)      // 3520 floats (t + p)
#define SWS    33                    // s_w column stride

#define INV_VOL (1.0f / 729.0f)
#define EPS 1e-5f

// dynamic smem: stages 3*3520 + s01 (2*40*33 float2 = 5280 f) + s2 (2640 f)
#define SMEM_FLOATS (3 * ST_BUF + 2 * 40 * SWS * 2 + 2 * 40 * SWS)
#define SMEM_BYTES  (SMEM_FLOATS * 4)   // 73920

__global__ void __launch_bounds__(NT, 1)
lncc_fused4(const float* __restrict__ gt, const float* __restrict__ gp,
            float* __restrict__ out)
{
    extern __shared__ float sm[];
    float*  stg = sm;                                  // [3][2][40][ST_ROW]
    float2* s01 = (float2*)(sm + 3 * ST_BUF);          // [2][40][SWS]
    float*  s2v = sm + 3 * ST_BUF + 2 * 40 * SWS * 2;  // [2][40][SWS]

    const int tid = threadIdx.x;
    const int bx  = blockIdx.x;
    const int wt  = bx % 6;
    const int ht  = (bx / 6) % 6;
    const int dc  = (bx / 36) % 2;
    const int bb  = bx / 72;
    const int w0 = wt * 32, h0 = ht * 32, d0 = dc * DCHUNK;
    const int gvol = bb * VOL;

    // pre-zero stages once: OOB lanes are never written and stay zero
    for (int i = tid; i < 3 * ST_BUF; i += NT) stg[i] = 0.f;
    __syncthreads();

    const uint32_t stg_base = (uint32_t)__cvta_generic_to_shared(stg);

    // ---- cp.async fill of one raw slice into stage sb ----
    auto fill = [&](int dz, int sb) {
        if ((unsigned)dz < DD) {
            const int dbase = gvol + dz * PLANE;
            for (int task = tid; task < 800; task += NT) {
                const int chunk = task % 10;          // float4 chunk 0..9
                const int rowf  = task / 10;          // 0..79 (t rows, then p)
                const int fld   = rowf >= 40 ? 1 : 0;
                const int row   = rowf - fld * 40;
                const int gh = h0 - 4 + row;
                const int gw = w0 - 4 + chunk * 4;
                if ((unsigned)gh < HH && (unsigned)gw < WW) {
                    const float* src = (fld ? gp : gt) + dbase + gh * WW + gw;
                    const uint32_t dst = stg_base +
                        (uint32_t)(sb * ST_BUF + fld * ST_FIELD +
                                   row * ST_ROW + chunk * 4) * 4u;
                    asm volatile("cp.async.cg.shared.global [%0], [%1], 16;"
                                 :: "r"(dst), "l"(src));
                }
            }
        }
        asm volatile("cp.async.commit_group;");
    };

    // ---- w-stage: 320 tasks (40 rows x 8 segs of 4 sliding W-sums) ----
    auto wstage = [&](int dz, int sb, int par) {
        const bool valid = (unsigned)dz < DD;
        for (int task = tid; task < 320; task += NT) {
            const int wr = task >> 3, ws = task & 7;
            float2* o01 = s01 + (par * 40 + wr) * SWS + ws * 4;
            float*  o2  = s2v + (par * 40 + wr) * SWS + ws * 4;
            if (valid) {
                const float* pt = stg + sb * ST_BUF + wr * ST_ROW + ws * 4;
                const float4 T0 = ((const float4*)pt)[0];
                const float4 T1 = ((const float4*)pt)[1];
                const float4 T2 = ((const float4*)pt)[2];
                const float* pp = pt + ST_FIELD;
                const float4 P0 = ((const float4*)pp)[0];
                const float4 P1 = ((const float4*)pp)[1];
                const float4 P2 = ((const float4*)pp)[2];
                const float t[12] = {T0.x,T0.y,T0.z,T0.w, T1.x,T1.y,T1.z,T1.w,
                                     T2.x,T2.y,T2.z,T2.w};
                const float p[12] = {P0.x,P0.y,P0.z,P0.w, P1.x,P1.y,P1.z,P1.w,
                                     P2.x,P2.y,P2.z,P2.w};
                float m[12];
#pragma unroll
                for (int k = 0; k < 12; ++k) m[k] = t[k] * p[k];
                float st = 0.f, sp = 0.f, stp = 0.f;
#pragma unroll
                for (int k = 0; k < 9; ++k) { st += t[k]; sp += p[k]; stp += m[k]; }
                o01[0] = make_float2(st, sp); o2[0] = stp;
#pragma unroll
                for (int q = 1; q < 4; ++q) {
                    st  += t[8 + q] - t[q - 1];
                    sp  += p[8 + q] - p[q - 1];
                    stp += m[8 + q] - m[q - 1];
                    o01[q] = make_float2(st, sp); o2[q] = stp;
                }
            } else {
#pragma unroll
                for (int q = 0; q < 4; ++q) {
                    o01[q] = make_float2(0.f, 0.f); o2[q] = 0.f;
                }
            }
        }
    };

    // ---- prime the async pipeline (slices d0-4, d0-3) ----
    fill(d0 - 4, 0);
    fill(d0 - 3, 1);

    // ---- iteration j = 0: w-stage only ----
    asm volatile("cp.async.wait_group 1;");
    __syncthreads();
    wstage(d0 - 4, 0, 0);
    fill(d0 - 2, 2);

    // ---- D ring: 8 deep x 4 outputs x 3 fields = 96 regs ----
    float ring[96];
    float S[12];
#pragma unroll
    for (int q = 0; q < 96; ++q) ring[q] = 0.f;
#pragma unroll
    for (int q = 0; q < 12; ++q) S[q] = 0.f;

    const int ty = tid >> 5, tx = tid & 31;
    const int rb = ty << 2;                       // 4 output rows per thread
    const int obase = gvol + (h0 + rb) * WW + w0 + tx;

    for (int blk = 0; blk < 13; ++blk) {
#pragma unroll
        for (int ph = 0; ph < 8; ++ph) {
            const int j = 1 + blk * 8 + ph;       // 1..104
            asm volatile("cp.async.wait_group 1;");
            __syncthreads();

            // -- h-stage: slice ingested last iter, parity (j-1)&1 --
            const int par_h = (j - 1) & 1;
            const float2* pr = s01 + (par_h * 40 + rb) * SWS + tx;
            const float*  qr = s2v + (par_h * 40 + rb) * SWS + tx;
            float2 u[12]; float v[12];
#pragma unroll
            for (int k = 0; k < 12; ++k) { u[k] = pr[k * SWS]; v[k] = qr[k * SWS]; }
            float hs0[4], hs1[4], hs2[4];
            {
                float a0 = u[0].x, a1 = u[0].y, a2 = v[0];
#pragma unroll
                for (int k = 1; k < 9; ++k) { a0 += u[k].x; a1 += u[k].y; a2 += v[k]; }
                hs0[0] = a0; hs1[0] = a1; hs2[0] = a2;
#pragma unroll
                for (int q = 1; q < 4; ++q) {
                    a0 += u[8 + q].x - u[q - 1].x;
                    a1 += u[8 + q].y - u[q - 1].y;
                    a2 += v[8 + q]   - v[q - 1];
                    hs0[q] = a0; hs1[q] = a1; hs2[q] = a2;
                }
            }

            // -- w-stage for slice d0-4+j; prefetch slice d0-2+j --
            if (j <= 103) wstage(d0 - 4 + j, j % 3, j & 1);
            if (j <= 102) fill(d0 - 2 + j, (j + 2) % 3);

            // -- ring update + fused epilogue (ph is compile-time) --
            const int d = d0 + j - 9;
#pragma unroll
            for (int q = 0; q < 4; ++q) {
                S[q * 3 + 0] += hs0[q];
                S[q * 3 + 1] += hs1[q];
                S[q * 3 + 2] += hs2[q];
                if (blk > 0) {
                    const float cross = S[q * 3 + 2] -
                        S[q * 3 + 1] * S[q * 3 + 0] * INV_VOL;
                    out[obase + d * PLANE + q * WW] = fmaf(cross, cross, EPS);
                    S[q * 3 + 0] -= ring[ph * 12 + q * 3 + 0];
                    S[q * 3 + 1] -= ring[ph * 12 + q * 3 + 1];
                    S[q * 3 + 2] -= ring[ph * 12 + q * 3 + 2];
                }
                ring[ph * 12 + q * 3 + 0] = hs0[q];
                ring[ph * 12 + q * 3 + 1] = hs1[q];
                ring[ph * 12 + q * 3 + 2] = hs2[q];
            }
        }
    }
}

extern "C" void kernel_launch(void* const* d_in, const int* in_sizes, int n_in,
                              void* d_out, int out_size) {
    const float* y_true = (const float*)d_in[0];
    const float* y_pred = (const float*)d_in[1];
    float* out = (float*)d_out;

    // >48KB dynamic smem needs the opt-in attribute (host state, capture-safe)
    cudaFuncSetAttribute(lncc_fused4,
                         cudaFuncAttributeMaxDynamicSharedMemorySize, SMEM_BYTES);

    // 6 w-tiles x 6 h-tiles x 2 d-chunks x 2 batches = 144 blocks (1 wave)
    lncc_fused4<<<144, NT, SMEM_BYTES>>>(y_true, y_pred, out);
}

// round 9
// speedup vs baseline: 1.3961x; 1.1623x over previous
#include <cuda_runtime.h>
#include <cstdint>

// (B, D, H, W) = (2, 192, 192, 192) fp32
#define DD 192
#define HH 192
#define WW 192
#define PLANE 36864
#define VOL   7077888

#define NT     512
#define DCHUNK 96
#define ST_ROW 44                    // stage row stride (floats), 16B-aligned
#define ST_FIELD (40 * ST_ROW)       // 1760 floats
#define ST_BUF   (2 * ST_FIELD)      // 3520 floats (t + p)
#define SWS    33                    // s_w column stride

#define INV_VOL (1.0f / 729.0f)
#define EPS 1e-5f

#define SMEM_FLOATS (3 * ST_BUF + 2 * 40 * SWS * 2 + 2 * 40 * SWS)
#define SMEM_BYTES  (SMEM_FLOATS * 4)   // 73920

// R9: same 3-stage cp.async skewed pipeline as R8 but 512 threads (16 warps)
// with a 2-outputs-per-thread h-stage so the d-ring fits 128 regs/thread.
__global__ void __launch_bounds__(NT, 1)
lncc_fused5(const float* __restrict__ gt, const float* __restrict__ gp,
            float* __restrict__ out)
{
    extern __shared__ float sm[];
    float*  stg = sm;                                  // [3][2][40][ST_ROW]
    float2* s01 = (float2*)(sm + 3 * ST_BUF);          // [2][40][SWS]
    float*  s2v = sm + 3 * ST_BUF + 2 * 40 * SWS * 2;  // [2][40][SWS]

    const int tid = threadIdx.x;
    const int bx  = blockIdx.x;
    const int wt  = bx % 6;
    const int ht  = (bx / 6) % 6;
    const int dc  = (bx / 36) % 2;
    const int bb  = bx / 72;
    const int w0 = wt * 32, h0 = ht * 32, d0 = dc * DCHUNK;
    const int gvol = bb * VOL;

    // pre-zero stages once: OOB lanes are never written and stay zero
    for (int i = tid; i < 3 * ST_BUF; i += NT) stg[i] = 0.f;
    __syncthreads();

    const uint32_t stg_base = (uint32_t)__cvta_generic_to_shared(stg);

    // ---- cp.async fill of one raw slice into stage sb ----
    auto fill = [&](int dz, int sb) {
        if ((unsigned)dz < DD) {
            const int dbase = gvol + dz * PLANE;
            for (int task = tid; task < 800; task += NT) {
                const int chunk = task % 10;          // float4 chunk 0..9
                const int rowf  = task / 10;          // 0..79 (t rows, then p)
                const int fld   = rowf >= 40 ? 1 : 0;
                const int row   = rowf - fld * 40;
                const int gh = h0 - 4 + row;
                const int gw = w0 - 4 + chunk * 4;
                if ((unsigned)gh < HH && (unsigned)gw < WW) {
                    const float* src = (fld ? gp : gt) + dbase + gh * WW + gw;
                    const uint32_t dst = stg_base +
                        (uint32_t)(sb * ST_BUF + fld * ST_FIELD +
                                   row * ST_ROW + chunk * 4) * 4u;
                    asm volatile("cp.async.cg.shared.global [%0], [%1], 16;"
                                 :: "r"(dst), "l"(src));
                }
            }
        }
        asm volatile("cp.async.commit_group;");
    };

    // ---- w-stage: 320 tasks (40 rows x 8 segs of 4 sliding W-sums) ----
    auto wstage = [&](int dz, int sb, int par) {
        const bool valid = (unsigned)dz < DD;
        for (int task = tid; task < 320; task += NT) {
            const int wr = task >> 3, ws = task & 7;
            float2* o01 = s01 + (par * 40 + wr) * SWS + ws * 4;
            float*  o2  = s2v + (par * 40 + wr) * SWS + ws * 4;
            if (valid) {
                const float* pt = stg + sb * ST_BUF + wr * ST_ROW + ws * 4;
                const float4 T0 = ((const float4*)pt)[0];
                const float4 T1 = ((const float4*)pt)[1];
                const float4 T2 = ((const float4*)pt)[2];
                const float* pp = pt + ST_FIELD;
                const float4 P0 = ((const float4*)pp)[0];
                const float4 P1 = ((const float4*)pp)[1];
                const float4 P2 = ((const float4*)pp)[2];
                const float t[12] = {T0.x,T0.y,T0.z,T0.w, T1.x,T1.y,T1.z,T1.w,
                                     T2.x,T2.y,T2.z,T2.w};
                const float p[12] = {P0.x,P0.y,P0.z,P0.w, P1.x,P1.y,P1.z,P1.w,
                                     P2.x,P2.y,P2.z,P2.w};
                float m[12];
#pragma unroll
                for (int k = 0; k < 12; ++k) m[k] = t[k] * p[k];
                float st = 0.f, sp = 0.f, stp = 0.f;
#pragma unroll
                for (int k = 0; k < 9; ++k) { st += t[k]; sp += p[k]; stp += m[k]; }
                o01[0] = make_float2(st, sp); o2[0] = stp;
#pragma unroll
                for (int q = 1; q < 4; ++q) {
                    st  += t[8 + q] - t[q - 1];
                    sp  += p[8 + q] - p[q - 1];
                    stp += m[8 + q] - m[q - 1];
                    o01[q] = make_float2(st, sp); o2[q] = stp;
                }
            } else {
#pragma unroll
                for (int q = 0; q < 4; ++q) {
                    o01[q] = make_float2(0.f, 0.f); o2[q] = 0.f;
                }
            }
        }
    };

    // ---- prime the async pipeline ----
    fill(d0 - 4, 0);
    fill(d0 - 3, 1);

    asm volatile("cp.async.wait_group 1;");
    __syncthreads();
    wstage(d0 - 4, 0, 0);
    fill(d0 - 2, 2);

    // ---- D ring: 8 deep x 2 outputs x 3 fields = 48 regs ----
    float ring[48];
    float S[6];
#pragma unroll
    for (int q = 0; q < 48; ++q) ring[q] = 0.f;
#pragma unroll
    for (int q = 0; q < 6; ++q) S[q] = 0.f;

    const int ty = tid >> 5, tx = tid & 31;
    const int rb = ty << 1;                       // 2 output rows per thread
    const int obase = gvol + (h0 + rb) * WW + w0 + tx;

    for (int blk = 0; blk < 13; ++blk) {
#pragma unroll
        for (int ph = 0; ph < 8; ++ph) {
            const int j = 1 + blk * 8 + ph;       // 1..104
            asm volatile("cp.async.wait_group 1;");
            __syncthreads();

            // -- h-stage: slice ingested last iter, parity (j-1)&1 --
            const int par_h = (j - 1) & 1;
            const float2* pr = s01 + (par_h * 40 + rb) * SWS + tx;
            const float*  qr = s2v + (par_h * 40 + rb) * SWS + tx;
            float2 u[10]; float v[10];
#pragma unroll
            for (int k = 0; k < 10; ++k) { u[k] = pr[k * SWS]; v[k] = qr[k * SWS]; }
            float a0 = u[0].x, a1 = u[0].y, a2 = v[0];
#pragma unroll
            for (int k = 1; k < 9; ++k) { a0 += u[k].x; a1 += u[k].y; a2 += v[k]; }
            const float b0 = a0 - u[0].x + u[9].x;
            const float b1 = a1 - u[0].y + u[9].y;
            const float b2 = a2 - v[0]   + v[9];

            // -- w-stage for slice d0-4+j; prefetch slice d0-2+j --
            if (j <= 103) wstage(d0 - 4 + j, j % 3, j & 1);
            if (j <= 102) fill(d0 - 2 + j, (j + 2) % 3);

            // -- ring update + fused epilogue (ph compile-time) --
            const int d = d0 + j - 9;
            S[0] += a0; S[1] += a1; S[2] += a2;
            S[3] += b0; S[4] += b1; S[5] += b2;
            if (blk > 0) {
                const float ca = S[2] - S[1] * S[0] * INV_VOL;
                const float cb = S[5] - S[4] * S[3] * INV_VOL;
                const int o = obase + d * PLANE;
                out[o]      = fmaf(ca, ca, EPS);
                out[o + WW] = fmaf(cb, cb, EPS);
                S[0] -= ring[ph * 6 + 0]; S[1] -= ring[ph * 6 + 1];
                S[2] -= ring[ph * 6 + 2]; S[3] -= ring[ph * 6 + 3];
                S[4] -= ring[ph * 6 + 4]; S[5] -= ring[ph * 6 + 5];
            }
            ring[ph * 6 + 0] = a0; ring[ph * 6 + 1] = a1;
            ring[ph * 6 + 2] = a2; ring[ph * 6 + 3] = b0;
            ring[ph * 6 + 4] = b1; ring[ph * 6 + 5] = b2;
        }
    }
}

extern "C" void kernel_launch(void* const* d_in, const int* in_sizes, int n_in,
                              void* d_out, int out_size) {
    const float* y_true = (const float*)d_in[0];
    const float* y_pred = (const float*)d_in[1];
    float* out = (float*)d_out;

    cudaFuncSetAttribute(lncc_fused5,
                         cudaFuncAttributeMaxDynamicSharedMemorySize, SMEM_BYTES);

    // 6 w-tiles x 6 h-tiles x 2 d-chunks x 2 batches = 144 blocks (1 wave)
    lncc_fused5<<<144, NT, SMEM_BYTES>>>(y_true, y_pred, out);
}

// round 11
// speedup vs baseline: 1.4996x; 1.0741x over previous
#include <cuda_runtime.h>
#include <cstdint>

// (B, D, H, W) = (2, 192, 192, 192) fp32
#define DD 192
#define HH 192
#define WW 192
#define PLANE 36864
#define VOL   7077888

#define NT     256
#define DCHUNK 96
#define INR    24                    // staged rows = 16 + 8 halo
#define ST_ROW 44                    // stage row stride (floats), 16B aligned
#define ST_FIELD (INR * ST_ROW)      // 1056
#define ST_BUF   (2 * ST_FIELD)      // 2112 floats (t + p)
#define SWS    33                    // s_w column stride

#define INV_VOL (1.0f / 729.0f)
#define EPS 1e-5f

// smem: 3 stage bufs + s01 (2 par x 24 x 33 float2) + s2 (2 x 24 x 33 float)
#define SMEM_FLOATS (3 * ST_BUF + 2 * INR * SWS * 2 + 2 * INR * SWS)
#define SMEM_BYTES  (SMEM_FLOATS * 4)   // 44352 -> 2 CTAs/SM

// R10: 2 CTAs/SM (tile 32w x 16h, 256 thr) + fully hoisted address math.
__global__ void __launch_bounds__(NT, 2)
lncc_fused6(const float* __restrict__ gt, const float* __restrict__ gp,
            float* __restrict__ out)
{
    extern __shared__ float sm[];
    float*  stg = sm;                                    // [3][2][24][ST_ROW]
    float2* s01 = (float2*)(sm + 3 * ST_BUF);            // [2][24][SWS]
    float*  s2v = sm + 3 * ST_BUF + 2 * INR * SWS * 2;   // [2][24][SWS]

    const int tid = threadIdx.x;
    const int bx  = blockIdx.x;
    const int wt  = bx % 6;
    const int ht  = (bx / 6) % 12;
    const int dc  = (bx / 72) % 2;
    const int bb  = bx / 144;
    const int w0 = wt * 32, h0 = ht * 16, d0 = dc * DCHUNK;
    const int gvol = bb * VOL;

    // pre-zero stages once: OOB lanes never written, stay zero
    for (int i = tid; i < 3 * ST_BUF; i += NT) stg[i] = 0.f;

    const uint32_t stg_base = (uint32_t)__cvta_generic_to_shared(stg);

    // ---------- hoisted fill geometry: 480 tasks = 48 rowf x 10 chunks ----
    // task k covers (row, field, chunk); only dz*PLANE varies per slice.
    const float* fsrc[2];
    uint32_t     fdst[2];
    bool         fok[2];
#pragma unroll
    for (int k = 0; k < 2; ++k) {
        const int task = tid + k * NT;
        bool ok = task < 480;
        const int chunk = task % 10;
        const int rowf  = task / 10;
        const int fld   = rowf >= INR ? 1 : 0;
        const int row   = rowf - fld * INR;
        const int gh = h0 - 4 + row;
        const int gw = w0 - 4 + chunk * 4;
        ok = ok && (unsigned)gh < HH && (unsigned)gw < WW;
        fok[k]  = ok;
        fsrc[k] = (fld ? gp : gt) + (gvol + gh * WW + gw);
        fdst[k] = stg_base + (uint32_t)(fld * ST_FIELD + row * ST_ROW +
                                        chunk * 4) * 4u;
    }

    auto fill = [&](int dz, int sb) {
        if ((unsigned)dz < DD) {
            const int off = dz * PLANE;
            const uint32_t dsb = (uint32_t)(sb * ST_BUF) * 4u;
#pragma unroll
            for (int k = 0; k < 2; ++k) {
                if (fok[k]) {
                    asm volatile("cp.async.cg.shared.global [%0], [%1], 16;"
                                 :: "r"(fdst[k] + dsb), "l"(fsrc[k] + off));
                }
            }
        }
        asm volatile("cp.async.commit_group;");
    };

    // ---------- hoisted w-stage geometry: 192 tasks (24 rows x 8 segs) ----
    const bool wact = tid < 192;
    const int wr = tid >> 3, ws = tid & 7;
    const int ptoff = wr * ST_ROW + ws * 4;              // within stage buf
    float2* wo01[2];
    float*  wo2[2];
#pragma unroll
    for (int pz = 0; pz < 2; ++pz) {
        wo01[pz] = s01 + (pz * INR + wr) * SWS + ws * 4;
        wo2[pz]  = s2v + (pz * INR + wr) * SWS + ws * 4;
    }

    auto wstage = [&](int dz, int sb, int par) {
        if (!wact) return;
        float2* o01 = wo01[par];
        float*  o2  = wo2[par];
        if ((unsigned)dz < DD) {
            const float* pt = stg + sb * ST_BUF + ptoff;
            const float4 T0 = ((const float4*)pt)[0];
            const float4 T1 = ((const float4*)pt)[1];
            const float4 T2 = ((const float4*)pt)[2];
            const float* pp = pt + ST_FIELD;
            const float4 P0 = ((const float4*)pp)[0];
            const float4 P1 = ((const float4*)pp)[1];
            const float4 P2 = ((const float4*)pp)[2];
            const float t[12] = {T0.x,T0.y,T0.z,T0.w, T1.x,T1.y,T1.z,T1.w,
                                 T2.x,T2.y,T2.z,T2.w};
            const float p[12] = {P0.x,P0.y,P0.z,P0.w, P1.x,P1.y,P1.z,P1.w,
                                 P2.x,P2.y,P2.z,P2.w};
            float m[12];
#pragma unroll
            for (int k = 0; k < 12; ++k) m[k] = t[k] * p[k];
            float st = 0.f, sp = 0.f, stp = 0.f;
#pragma unroll
            for (int k = 0; k < 9; ++k) { st += t[k]; sp += p[k]; stp += m[k]; }
            o01[0] = make_float2(st, sp); o2[0] = stp;
#pragma unroll
            for (int q = 1; q < 4; ++q) {
                st  += t[8 + q] - t[q - 1];
                sp  += p[8 + q] - p[q - 1];
                stp += m[8 + q] - m[q - 1];
                o01[q] = make_float2(st, sp); o2[q] = stp;
            }
        } else {
#pragma unroll
            for (int q = 0; q < 4; ++q) {
                o01[q] = make_float2(0.f, 0.f); o2[q] = 0.f;
            }
        }
    };

    // ---------- hoisted h-stage geometry: 2 h-outputs per thread ----------
    const int ty = tid >> 5, tx = tid & 31;
    const int rb = ty << 1;                              // 0..14
    const float2* hp[2];
    const float*  hq[2];
#pragma unroll
    for (int pz = 0; pz < 2; ++pz) {
        hp[pz] = s01 + (pz * INR + rb) * SWS + tx;
        hq[pz] = s2v + (pz * INR + rb) * SWS + tx;
    }

    __syncthreads();   // stage pre-zero visible

    // ---- prime the async pipeline ----
    fill(d0 - 4, 0);
    fill(d0 - 3, 1);

    asm volatile("cp.async.wait_group 1;");
    __syncthreads();
    wstage(d0 - 4, 0, 0);
    fill(d0 - 2, 2);

    // ---- D ring: 8 deep x 2 outputs x 3 fields = 48 regs ----
    float ring[48];
    float S[6];
#pragma unroll
    for (int q = 0; q < 48; ++q) ring[q] = 0.f;
#pragma unroll
    for (int q = 0; q < 6; ++q) S[q] = 0.f;

    const int obase = gvol + (h0 + rb) * WW + w0 + tx;

    for (int blk = 0; blk < 13; ++blk) {
#pragma unroll
        for (int ph = 0; ph < 8; ++ph) {
            const int j = 1 + blk * 8 + ph;       // 1..104
            asm volatile("cp.async.wait_group 1;");
            __syncthreads();

            // -- h-stage: slice ingested last iter, parity (j-1)&1 --
            const float2* pr = hp[(j - 1) & 1];
            const float*  qr = hq[(j - 1) & 1];
            float2 u[10]; float v[10];
#pragma unroll
            for (int k = 0; k < 10; ++k) { u[k] = pr[k * SWS]; v[k] = qr[k * SWS]; }
            float a0 = u[0].x, a1 = u[0].y, a2 = v[0];
#pragma unroll
            for (int k = 1; k < 9; ++k) { a0 += u[k].x; a1 += u[k].y; a2 += v[k]; }
            const float b0 = a0 - u[0].x + u[9].x;
            const float b1 = a1 - u[0].y + u[9].y;
            const float b2 = a2 - v[0]   + v[9];

            // -- w-stage slice d0-4+j; prefetch slice d0-2+j --
            if (j <= 103) wstage(d0 - 4 + j, j % 3, j & 1);
            if (j <= 102) fill(d0 - 2 + j, (j + 2) % 3);

            // -- ring update + fused epilogue (ph compile-time) --
            const int d = d0 + j - 9;
            S[0] += a0; S[1] += a1; S[2] += a2;
            S[3] += b0; S[4] += b1; S[5] += b2;
            if (blk > 0) {
                const float ca = S[2] - S[1] * S[0] * INV_VOL;
                const float cb = S[5] - S[4] * S[3] * INV_VOL;
                const int o = obase + d * PLANE;
                out[o]      = fmaf(ca, ca, EPS);
                out[o + WW] = fmaf(cb, cb, EPS);
                S[0] -= ring[ph * 6 + 0]; S[1] -= ring[ph * 6 + 1];
                S[2] -= ring[ph * 6 + 2]; S[3] -= ring[ph * 6 + 3];
                S[4] -= ring[ph * 6 + 4]; S[5] -= ring[ph * 6 + 5];
            }
            ring[ph * 6 + 0] = a0; ring[ph * 6 + 1] = a1;
            ring[ph * 6 + 2] = a2; ring[ph * 6 + 3] = b0;
            ring[ph * 6 + 4] = b1; ring[ph * 6 + 5] = b2;
        }
    }
}

extern "C" void kernel_launch(void* const* d_in, const int* in_sizes, int n_in,
                              void* d_out, int out_size) {
    const float* y_true = (const float*)d_in[0];
    const float* y_pred = (const float*)d_in[1];
    float* out = (float*)d_out;

    cudaFuncSetAttribute(lncc_fused6,
                         cudaFuncAttributeMaxDynamicSharedMemorySize, SMEM_BYTES);

    // 6 w-tiles x 12 h-tiles x 2 d-chunks x 2 batches = 288 blocks (2 CTAs/SM)
    lncc_fused6<<<288, NT, SMEM_BYTES>>>(y_true, y_pred, out);
}

// round 12
// speedup vs baseline: 1.7123x; 1.1418x over previous
#include <cuda_runtime.h>
#include <cstdint>

// (B, D, H, W) = (2, 192, 192, 192) fp32
#define DD 192
#define HH 192
#define WW 192
#define PLANE 36864
#define VOL   7077888

#define NT 256
#define INR 24                     // staged rows = 16 + 8 halo
#define ST_ROW 44                  // stage row stride (floats)
#define ST_FIELD 1056              // 24*44
#define ST_SLICE 2112              // t + p
#define WSTR 33                    // W-sum row stride
#define WFLD 792                   // 24*33 per field
#define WSL  2376                  // 3 fields per slice
#define WPAR 4752                  // 2 slices per parity set

#define INV_VOL (1.0f/729.0f)
#define EPS 1e-5f

// smem: 6 slice stage bufs (3 sets x 2) + 2 W-sum parity sets (2 slices each)
#define SMEM_FLOATS (6*ST_SLICE + 2*WPAR)   // 22176
#define SMEM_BYTES  (SMEM_FLOATS*4)          // 88704 -> 2 CTAs/SM

// R12: pair-batched pipeline (1 barrier / 2 slices), 8-wide w-segments,
// 2-iteration cp.async lookahead, 2 CTAs/SM.
__global__ void __launch_bounds__(NT, 2)
lncc_fused7(const float* __restrict__ gt, const float* __restrict__ gp,
            float* __restrict__ out)
{
    extern __shared__ float sm[];
    float* stg = sm;                 // [3 sets][2 sl][2 fld][24][44]
    float* ws  = sm + 6*ST_SLICE;    // [2 par][2 sl][3 fld][24][33]

    const int tid = threadIdx.x;
    const int bx = blockIdx.x;
    const int wt = bx % 6;
    const int ht = (bx/6) % 12;
    const int dc = (bx/72) % 2;
    const int bb = bx/144;
    const int w0 = wt*32, h0 = ht*16, d0 = dc*96;
    const int gvol = bb*VOL;

    // zero stage once: OOB (h/w halo) lanes are never overwritten
    for (int i = tid; i < 6*ST_SLICE; i += NT) stg[i] = 0.f;

    const uint32_t stg_base = (uint32_t)__cvta_generic_to_shared(stg);

    // ---- hoisted fill geometry: 480 tasks = 48 rowf x 10 float4 chunks ----
    const float* fsrc[2]; uint32_t fdst[2]; bool fok[2];
#pragma unroll
    for (int k = 0; k < 2; ++k) {
        const int task = tid + k*NT;
        bool ok = task < 480;
        const int chunk = task % 10;
        const int rowf  = task / 10;
        const int fld   = rowf >= INR ? 1 : 0;
        const int row   = rowf - fld*INR;
        const int gh = h0 - 4 + row;
        const int gw = w0 - 4 + chunk*4;
        ok = ok && (unsigned)gh < HH && (unsigned)gw < WW;
        fok[k]  = ok;
        fsrc[k] = (fld ? gp : gt) + (gvol + gh*WW + gw);
        fdst[k] = stg_base + (uint32_t)(fld*ST_FIELD + row*ST_ROW + chunk*4)*4u;
    }

    auto fill_pair = [&](int pair, int rset) {
#pragma unroll
        for (int sl = 0; sl < 2; ++sl) {
            const int dz = d0 - 4 + 2*pair + sl;
            if ((unsigned)dz < DD) {
                const int off = dz*PLANE;
                const uint32_t dsb = (uint32_t)((rset*2+sl)*ST_SLICE)*4u;
#pragma unroll
                for (int k = 0; k < 2; ++k)
                    if (fok[k])
                        asm volatile("cp.async.cg.shared.global [%0], [%1], 16;"
                                     :: "r"(fdst[k]+dsb), "l"(fsrc[k]+off));
            }
        }
        asm volatile("cp.async.commit_group;");
    };

    // ---- hoisted w geometry: per pair 192 tasks = 2 sl x 24 rows x 4 segs8 ----
    const bool wact = tid < 192;
    const int wsl  = tid >= 96 ? 1 : 0;
    const int wsub = tid - wsl*96;
    const int wr   = wsub >> 2, ws4 = wsub & 3;
    const int wroff = wsl*ST_SLICE + wr*ST_ROW + ws4*8;   // + rset*2*ST_SLICE
    const int wcout = wsl*WSL + wr*WSTR + ws4*8;          // + par*WPAR

    auto wstage_pair = [&](int pair, int rset, int par) {
        if (!wact) return;
        const int dz = d0 - 4 + 2*pair + wsl;
        float* o = ws + par*WPAR + wcout;
        if ((unsigned)dz < DD) {
            const float* pt = stg + rset*2*ST_SLICE + wroff;
            const float4 T0 = ((const float4*)pt)[0];
            const float4 T1 = ((const float4*)pt)[1];
            const float4 T2 = ((const float4*)pt)[2];
            const float4 T3 = ((const float4*)pt)[3];
            const float* pq = pt + ST_FIELD;
            const float4 P0 = ((const float4*)pq)[0];
            const float4 P1 = ((const float4*)pq)[1];
            const float4 P2 = ((const float4*)pq)[2];
            const float4 P3 = ((const float4*)pq)[3];
            const float t[16] = {T0.x,T0.y,T0.z,T0.w, T1.x,T1.y,T1.z,T1.w,
                                 T2.x,T2.y,T2.z,T2.w, T3.x,T3.y,T3.z,T3.w};
            const float p[16] = {P0.x,P0.y,P0.z,P0.w, P1.x,P1.y,P1.z,P1.w,
                                 P2.x,P2.y,P2.z,P2.w, P3.x,P3.y,P3.z,P3.w};
            float st = 0.f, sp = 0.f, stp = 0.f;
#pragma unroll
            for (int k = 0; k < 9; ++k) {
                st += t[k]; sp += p[k]; stp = fmaf(t[k], p[k], stp);
            }
            o[0] = st; o[WFLD] = sp; o[2*WFLD] = stp;
#pragma unroll
            for (int q = 1; q < 8; ++q) {
                st += t[8+q] - t[q-1];
                sp += p[8+q] - p[q-1];
                stp = fmaf(t[8+q], p[8+q], stp);
                stp = fmaf(-t[q-1], p[q-1], stp);
                o[q] = st; o[WFLD+q] = sp; o[2*WFLD+q] = stp;
            }
        } else {
#pragma unroll
            for (int q = 0; q < 8; ++q) {
                o[q] = 0.f; o[WFLD+q] = 0.f; o[2*WFLD+q] = 0.f;
            }
        }
    };

    // ---- h geometry: 2 consecutive h-outputs per thread ----
    const int ty = tid >> 5, tx = tid & 31;
    const int rb = ty << 1;
    const int rbtx = rb*WSTR + tx;
    const int obase = gvol + (h0+rb)*WW + w0 + tx;

    float ring[48], S[6];
#pragma unroll
    for (int q = 0; q < 48; ++q) ring[q] = 0.f;
#pragma unroll
    for (int q = 0; q < 6; ++q) S[q] = 0.f;

// ingest one slice's HW-sums into ring + fused epilogue; PH compile-time
#define H_SLICE(PAR, SL, PH, DOOUT, DOFS) do {                               \
    const float* hb = ws + (PAR)*WPAR + (SL)*WSL + rbtx;                     \
    float u[10];                                                             \
    float a0,a1,a2,b0,b1,b2;                                                 \
    _Pragma("unroll") for (int k=0;k<10;++k) u[k]=hb[k*WSTR];                \
    a0=((u[0]+u[1])+(u[2]+u[3]))+((u[4]+u[5])+(u[6]+u[7]))+u[8];             \
    b0=a0-u[0]+u[9];                                                         \
    _Pragma("unroll") for (int k=0;k<10;++k) u[k]=hb[WFLD+k*WSTR];           \
    a1=((u[0]+u[1])+(u[2]+u[3]))+((u[4]+u[5])+(u[6]+u[7]))+u[8];             \
    b1=a1-u[0]+u[9];                                                         \
    _Pragma("unroll") for (int k=0;k<10;++k) u[k]=hb[2*WFLD+k*WSTR];         \
    a2=((u[0]+u[1])+(u[2]+u[3]))+((u[4]+u[5])+(u[6]+u[7]))+u[8];             \
    b2=a2-u[0]+u[9];                                                         \
    S[0]+=a0; S[1]+=a1; S[2]+=a2; S[3]+=b0; S[4]+=b1; S[5]+=b2;              \
    if (DOOUT) {                                                             \
        const float ca = S[2]-S[1]*S[0]*INV_VOL;                             \
        const float cb = S[5]-S[4]*S[3]*INV_VOL;                             \
        const int oo = obase + (DOFS)*PLANE;                                 \
        out[oo]      = fmaf(ca,ca,EPS);                                      \
        out[oo + WW] = fmaf(cb,cb,EPS);                                      \
    }                                                                        \
    S[0]-=ring[(PH)*6+0]; S[1]-=ring[(PH)*6+1]; S[2]-=ring[(PH)*6+2];        \
    S[3]-=ring[(PH)*6+3]; S[4]-=ring[(PH)*6+4]; S[5]-=ring[(PH)*6+5];        \
    ring[(PH)*6+0]=a0; ring[(PH)*6+1]=a1; ring[(PH)*6+2]=a2;                 \
    ring[(PH)*6+3]=b0; ring[(PH)*6+4]=b1; ring[(PH)*6+5]=b2;                 \
} while(0)

    __syncthreads();                 // stage zeros visible
    fill_pair(0, 0);
    fill_pair(1, 1);

    // 52 pairs (104 slices: dz = d0-4 .. d0+99)
    for (int bq = 0; bq < 13; ++bq) {
#pragma unroll
        for (int ii = 0; ii < 4; ++ii) {
            const int i = bq*4 + ii;          // pair index 0..51
            asm volatile("cp.async.wait_group 1;");
            __syncthreads();
            if (i > 0) {
                const bool dout = (i >= 5);
                // h-slices t0=2i-2, t1=2i-1 from parity (i-1)&1 = (ii+1)&1
                H_SLICE((ii+1)&1, 0, (2*ii+6)&7, dout, d0+2*i-10);
                H_SLICE((ii+1)&1, 1, (2*ii+7)&7, dout, d0+2*i-9);
            }
            wstage_pair(i, i%3, ii&1);
            if (i <= 49) fill_pair(i+2, (i+2)%3);
            else         asm volatile("cp.async.commit_group;");
        }
    }
    // final pair (t=102,103 -> outputs d0+94, d0+95)
    __syncthreads();
    H_SLICE(1, 0, 6, true, d0+94);
    H_SLICE(1, 1, 7, true, d0+95);
#undef H_SLICE
}

extern "C" void kernel_launch(void* const* d_in, const int* in_sizes, int n_in,
                              void* d_out, int out_size) {
    const float* y_true = (const float*)d_in[0];
    const float* y_pred = (const float*)d_in[1];
    float* out = (float*)d_out;

    cudaFuncSetAttribute(lncc_fused7,
                         cudaFuncAttributeMaxDynamicSharedMemorySize, SMEM_BYTES);

    // 6 w-tiles x 12 h-tiles x 2 d-chunks x 2 batches = 288 blocks (2 CTAs/SM)
    lncc_fused7<<<288, NT, SMEM_BYTES>>>(y_true, y_pred, out);
}